// round 5
// baseline (speedup 1.0000x reference)
#include <cuda_runtime.h>
#include <math.h>

// Problem constants
#define NIMG 8
#define CCH  3
#define HI   512
#define WI   512
#define HO   2048
#define WO   2048

// Per-layer affine params: a, tx, b, ty
__device__ float4 g_prm[NIMG];
// Coverage box in output px (inclusive): x_lo, x_hi, y_lo, y_hi
__device__ int4 g_cov[NIMG];
// Interior box in output px (inclusive, conservative): xi_lo, xi_hi, yi_lo, yi_hi
__device__ int4 g_int[NIMG];

__device__ __forceinline__ float sigm(float z) {
    return 1.0f / (1.0f + expf(-z));
}

// Shared coordinate evaluators — used by BOTH kernels so classification in
// prm_kernel matches the main kernel's arithmetic.
__device__ __forceinline__ float ix_at(int px, float a, float tx) {
    float xs = (float)(2 * px + 1) * (1.0f / (float)WO) - 1.0f;
    float gx = a * xs + tx;
    return ((gx + 1.0f) * (float)WI - 1.0f) * 0.5f;
}
__device__ __forceinline__ float iy_at(int py, float b, float ty) {
    float ys = (float)(2 * py + 1) * (1.0f / (float)HO) - 1.0f;
    float gy = b * ys + ty;
    return ((gy + 1.0f) * (float)HI - 1.0f) * 0.5f;
}

__global__ void prm_kernel(const float* __restrict__ coor) {
    int n = threadIdx.x;
    if (n >= NIMG) return;

    float x = sigm(coor[4 * n + 0]) * (float)WO;
    float y = sigm(coor[4 * n + 1]) * (float)HO;
    float w = sigm(coor[4 * n + 2]) * (float)WO;
    float h = sigm(coor[4 * n + 3]) * (float)HO;
    float a  = (float)WO / (w + 1e-8f);
    float tx = (2.0f / (float)WO) * ((float)WO * 0.5f - x) * a;
    float b  = (float)HO / (h + 1e-8f);
    float ty = (2.0f / (float)HO) * ((float)HO * 0.5f - y) * b;
    g_prm[n] = make_float4(a, tx, b, ty);

    // ix/iy are strictly increasing in px/py (a>0, b>0).
    // first_true(pred) over [0, N): pred monotone false->true.
    auto first_true_x = [&](float thresh) {
        // first px with ix_at(px) >= thresh
        int lo = 0, hi = WO;
        while (lo < hi) { int m = (lo + hi) >> 1;
            if (ix_at(m, a, tx) >= thresh) hi = m; else lo = m + 1; }
        return lo;
    };
    auto first_true_x_gt = [&](float thresh) {
        // first px with ix_at(px) > thresh
        int lo = 0, hi = WO;
        while (lo < hi) { int m = (lo + hi) >> 1;
            if (ix_at(m, a, tx) > thresh) hi = m; else lo = m + 1; }
        return lo;
    };
    auto first_true_y = [&](float thresh) {
        int lo = 0, hi = HO;
        while (lo < hi) { int m = (lo + hi) >> 1;
            if (iy_at(m, b, ty) >= thresh) hi = m; else lo = m + 1; }
        return lo;
    };
    auto first_true_y_gt = [&](float thresh) {
        int lo = 0, hi = HO;
        while (lo < hi) { int m = (lo + hi) >> 1;
            if (iy_at(m, b, ty) > thresh) hi = m; else lo = m + 1; }
        return lo;
    };

    // Coverage: active iff ix > -1 && ix < WI   (iy likewise, strict)
    int x_lo = first_true_x_gt(-1.0f);
    int x_hi = first_true_x((float)WI) - 1;          // last px with ix < WI
    int y_lo = first_true_y_gt(-1.0f);
    int y_hi = first_true_y((float)HI) - 1;
    g_cov[n] = make_int4(x_lo, x_hi, y_lo, y_hi);

    // Interior (conservative by 1e-3 source px): 0 <= ix < WI-1, 0 <= iy < HI-1
    int xi_lo = first_true_x(1e-3f);
    int xi_hi = first_true_x((float)(WI - 1) - 1e-3f) - 1;
    int yi_lo = first_true_y(1e-3f);
    int yi_hi = first_true_y((float)(HI - 1) - 1e-3f) - 1;
    g_int[n] = make_int4(xi_lo, xi_hi, yi_lo, yi_hi);
}

// Back-to-front compositing, 8 px per thread, early termination when a
// fully-interior layer (m==1) covers the whole group.
__global__ __launch_bounds__(256, 3) void composite_kernel(
    const float* __restrict__ src,   // [8,3,512,512]
    const float* __restrict__ bg,    // [1,3,2048,2048]
    float* __restrict__ out)         // [1,3,2048,2048]
{
    const int px0 = (blockIdx.x * 32 + threadIdx.x) * 8;
    const int py  = blockIdx.y * 8 + threadIdx.y;
    const int HW  = HO * WO;
    const int base = py * WO + px0;

    float A[3][8];
    float T[8];
#pragma unroll
    for (int j = 0; j < 8; j++) {
        A[0][j] = 0.f; A[1][j] = 0.f; A[2][j] = 0.f; T[j] = 1.f;
    }

#pragma unroll
    for (int n = NIMG - 1; n >= 0; n--) {
        const int4 cv = g_cov[n];
        if (py < cv.z || py > cv.w || px0 + 7 < cv.x || px0 > cv.y) continue;

        const float4 p = g_prm[n];   // a, tx, b, ty
        const float iy = iy_at(py, p.z, p.w);

        const float y0f = floorf(iy);
        const float wy1 = iy - y0f;
        const float wy0 = 1.0f - wy1;
        const int   y0  = (int)y0f;
        const int   y1  = y0 + 1;
        const float* sbase = src + (size_t)n * CCH * HI * WI;

        const int4 it = g_int[n];
        const bool interior = (py >= it.z && py <= it.w &&
                               px0 >= it.x && px0 + 7 <= it.y);

        if (interior) {
            // m == 1 for all 8 px: this layer overwrites everything below.
            const float* r0 = sbase + y0 * WI;
            const float* r1 = r0 + WI;
#pragma unroll
            for (int j = 0; j < 8; j++) {
                const float ix = ix_at(px0 + j, p.x, p.y);
                const float x0f = floorf(ix);
                const float wx1 = ix - x0f;
                const float wx0 = 1.0f - wx1;
                const int   x0  = (int)x0f;
                const float w00 = wy0 * wx0, w10 = wy1 * wx0;
                const float w01 = wy0 * wx1, w11 = wy1 * wx1;
#pragma unroll
                for (int c = 0; c < CCH; c++) {
                    const float* rc0 = r0 + c * (HI * WI);
                    const float* rc1 = r1 + c * (HI * WI);
                    const float v00 = __ldg(rc0 + x0);
                    const float v10 = __ldg(rc1 + x0);
                    const float v01 = __ldg(rc0 + x0 + 1);
                    const float v11 = __ldg(rc1 + x0 + 1);
                    const float s = v00 * w00 + v10 * w10 + v01 * w01 + v11 * w11;
                    A[c][j] = fmaf(T[j], s, A[c][j]);
                }
                T[j] = 0.0f;
            }
            break;   // group fully opaque: earlier layers + bg invisible
        } else {
            // Boundary path: full reference semantics (validity + clamps).
            const float wyv0 = (y0 >= 0 && y0 < HI) ? wy0 : 0.0f;
            const float wyv1 = (y1 >= 0 && y1 < HI) ? wy1 : 0.0f;
            const int y0c = min(max(y0, 0), HI - 1);
            const int y1c = min(max(y1, 0), HI - 1);
            const float my = wyv0 + wyv1;
            const float* r0 = sbase + y0c * WI;
            const float* r1 = sbase + y1c * WI;
#pragma unroll
            for (int j = 0; j < 8; j++) {
                const float ix = ix_at(px0 + j, p.x, p.y);
                const float x0f = floorf(ix);
                const float wx1 = ix - x0f;
                const float wx0 = 1.0f - wx1;
                const int   x0  = (int)x0f;
                const int   x1  = x0 + 1;
                const float wxv0 = (x0 >= 0 && x0 < WI) ? wx0 : 0.0f;
                const float wxv1 = (x1 >= 0 && x1 < WI) ? wx1 : 0.0f;
                const int x0c = min(max(x0, 0), WI - 1);
                const int x1c = min(max(x1, 0), WI - 1);

                const float m = my * (wxv0 + wxv1);
                if (m == 0.0f) continue;
                const float wgt = T[j] * m;
#pragma unroll
                for (int c = 0; c < CCH; c++) {
                    const float* rc0 = r0 + c * (HI * WI);
                    const float* rc1 = r1 + c * (HI * WI);
                    const float v00 = __ldg(rc0 + x0c);
                    const float v10 = __ldg(rc1 + x0c);
                    const float v01 = __ldg(rc0 + x1c);
                    const float v11 = __ldg(rc1 + x1c);
                    const float rowA = v00 * wyv0 + v10 * wyv1;
                    const float rowB = v01 * wyv0 + v11 * wyv1;
                    const float s = rowA * wxv0 + rowB * wxv1;
                    A[c][j] = fmaf(wgt, s, A[c][j]);
                }
                T[j] *= (1.0f - m);
            }
        }
    }

    // Background contribution only where transparency survives.
    float Tm = T[0];
#pragma unroll
    for (int j = 1; j < 8; j++) Tm = fmaxf(Tm, T[j]);
    if (Tm > 0.0f) {
#pragma unroll
        for (int c = 0; c < CCH; c++) {
            const float4 b0 = *reinterpret_cast<const float4*>(bg + c * HW + base);
            const float4 b1 = *reinterpret_cast<const float4*>(bg + c * HW + base + 4);
            A[c][0] = fmaf(b0.x, T[0], A[c][0]);
            A[c][1] = fmaf(b0.y, T[1], A[c][1]);
            A[c][2] = fmaf(b0.z, T[2], A[c][2]);
            A[c][3] = fmaf(b0.w, T[3], A[c][3]);
            A[c][4] = fmaf(b1.x, T[4], A[c][4]);
            A[c][5] = fmaf(b1.y, T[5], A[c][5]);
            A[c][6] = fmaf(b1.z, T[6], A[c][6]);
            A[c][7] = fmaf(b1.w, T[7], A[c][7]);
        }
    }

#pragma unroll
    for (int c = 0; c < CCH; c++) {
        *reinterpret_cast<float4*>(out + c * HW + base) =
            make_float4(A[c][0], A[c][1], A[c][2], A[c][3]);
        *reinterpret_cast<float4*>(out + c * HW + base + 4) =
            make_float4(A[c][4], A[c][5], A[c][6], A[c][7]);
    }
}

extern "C" void kernel_launch(void* const* d_in, const int* in_sizes, int n_in,
                              void* d_out, int out_size) {
    const float* src  = (const float*)d_in[0];  // [8,3,512,512]
    const float* bg   = (const float*)d_in[1];  // [1,3,2048,2048]
    const float* coor = (const float*)d_in[2];  // [8,4]
    float* out = (float*)d_out;                 // [1,3,2048,2048]

    prm_kernel<<<1, 32>>>(coor);

    dim3 block(32, 8);
    dim3 grid(WO / (8 * 32), HO / 8);   // (8, 256)
    composite_kernel<<<grid, block>>>(src, bg, out);
}

// round 6
// speedup vs baseline: 1.1750x; 1.1750x over previous
#include <cuda_runtime.h>
#include <math.h>

// Problem constants
#define NIMG 8
#define CCH  3
#define HI   512
#define WI   512
#define HO   2048
#define WO   2048

// Per-layer affine params: a, tx, b, ty
__device__ float4 g_prm[NIMG];
// Coverage box in output px (inclusive): x_lo, x_hi, y_lo, y_hi
__device__ int4 g_cov[NIMG];
// Interior box in output px (inclusive, conservative): xi_lo, xi_hi, yi_lo, yi_hi
__device__ int4 g_int[NIMG];

__device__ __forceinline__ float sigm(float z) {
    return 1.0f / (1.0f + expf(-z));
}

// Shared coordinate evaluators — used by BOTH kernels so classification in
// prm_kernel matches the main kernel's arithmetic exactly.
__device__ __forceinline__ float ix_at(int px, float a, float tx) {
    float xs = (float)(2 * px + 1) * (1.0f / (float)WO) - 1.0f;
    float gx = a * xs + tx;
    return ((gx + 1.0f) * (float)WI - 1.0f) * 0.5f;
}
__device__ __forceinline__ float iy_at(int py, float b, float ty) {
    float ys = (float)(2 * py + 1) * (1.0f / (float)HO) - 1.0f;
    float gy = b * ys + ty;
    return ((gy + 1.0f) * (float)HI - 1.0f) * 0.5f;
}

__global__ void prm_kernel(const float* __restrict__ coor) {
    int n = threadIdx.x;
    if (n >= NIMG) return;

    float x = sigm(coor[4 * n + 0]) * (float)WO;
    float y = sigm(coor[4 * n + 1]) * (float)HO;
    float w = sigm(coor[4 * n + 2]) * (float)WO;
    float h = sigm(coor[4 * n + 3]) * (float)HO;
    float a  = (float)WO / (w + 1e-8f);
    float tx = (2.0f / (float)WO) * ((float)WO * 0.5f - x) * a;
    float b  = (float)HO / (h + 1e-8f);
    float ty = (2.0f / (float)HO) * ((float)HO * 0.5f - y) * b;
    g_prm[n] = make_float4(a, tx, b, ty);

    // ix/iy strictly increasing in px/py (a>0, b>0): binary-search thresholds.
    auto first_x_ge = [&](float thresh) {
        int lo = 0, hi = WO;
        while (lo < hi) { int m = (lo + hi) >> 1;
            if (ix_at(m, a, tx) >= thresh) hi = m; else lo = m + 1; }
        return lo;
    };
    auto first_x_gt = [&](float thresh) {
        int lo = 0, hi = WO;
        while (lo < hi) { int m = (lo + hi) >> 1;
            if (ix_at(m, a, tx) > thresh) hi = m; else lo = m + 1; }
        return lo;
    };
    auto first_y_ge = [&](float thresh) {
        int lo = 0, hi = HO;
        while (lo < hi) { int m = (lo + hi) >> 1;
            if (iy_at(m, b, ty) >= thresh) hi = m; else lo = m + 1; }
        return lo;
    };
    auto first_y_gt = [&](float thresh) {
        int lo = 0, hi = HO;
        while (lo < hi) { int m = (lo + hi) >> 1;
            if (iy_at(m, b, ty) > thresh) hi = m; else lo = m + 1; }
        return lo;
    };

    // Coverage: active iff ix > -1 && ix < WI (strict); iy likewise.
    g_cov[n] = make_int4(first_x_gt(-1.0f), first_x_ge((float)WI) - 1,
                         first_y_gt(-1.0f), first_y_ge((float)HI) - 1);

    // Interior (conservative 1e-3 source px): 0 <= ix < WI-1, 0 <= iy < HI-1.
    g_int[n] = make_int4(first_x_ge(1e-3f),
                         first_x_ge((float)(WI - 1) - 1e-3f) - 1,
                         first_y_ge(1e-3f),
                         first_y_ge((float)(HI - 1) - 1e-3f) - 1);
}

// Back-to-front compositing, 4 px per thread, early termination when a
// fully-interior layer (m==1) covers the whole group.
__global__ __launch_bounds__(128) void composite_kernel(
    const float* __restrict__ src,   // [8,3,512,512]
    const float* __restrict__ bg,    // [1,3,2048,2048]
    float* __restrict__ out)         // [1,3,2048,2048]
{
    const int px0 = (blockIdx.x * 32 + threadIdx.x) * 4;
    const int py  = blockIdx.y * 4 + threadIdx.y;
    const int HW  = HO * WO;
    const int base = py * WO + px0;

    float A[3][4] = {{0.f,0.f,0.f,0.f},{0.f,0.f,0.f,0.f},{0.f,0.f,0.f,0.f}};
    float T[4] = {1.f, 1.f, 1.f, 1.f};

#pragma unroll
    for (int n = NIMG - 1; n >= 0; n--) {
        const int4 cv = g_cov[n];
        if (py < cv.z || py > cv.w || px0 + 3 < cv.x || px0 > cv.y) continue;

        const float4 p = g_prm[n];   // a, tx, b, ty
        const float iy = iy_at(py, p.z, p.w);

        const float y0f = floorf(iy);
        const float wy1 = iy - y0f;
        const float wy0 = 1.0f - wy1;
        const int   y0  = (int)y0f;
        const int   y1  = y0 + 1;
        const float* sbase = src + (size_t)n * CCH * HI * WI;

        const int4 it = g_int[n];
        const bool interior = (py >= it.z && py <= it.w &&
                               px0 >= it.x && px0 + 3 <= it.y);

        if (interior) {
            // m == 1 for all 4 px: this layer overwrites everything below.
            const float* r0 = sbase + y0 * WI;
            const float* r1 = r0 + WI;
#pragma unroll
            for (int j = 0; j < 4; j++) {
                const float ix = ix_at(px0 + j, p.x, p.y);
                const float x0f = floorf(ix);
                const float wx1 = ix - x0f;
                const float wx0 = 1.0f - wx1;
                const int   x0  = (int)x0f;
#pragma unroll
                for (int c = 0; c < CCH; c++) {
                    const float* rc0 = r0 + c * (HI * WI);
                    const float* rc1 = r1 + c * (HI * WI);
                    const float v00 = __ldg(rc0 + x0);
                    const float v10 = __ldg(rc1 + x0);
                    const float v01 = __ldg(rc0 + x0 + 1);
                    const float v11 = __ldg(rc1 + x0 + 1);
                    const float rowA = v00 * wy0 + v10 * wy1;
                    const float rowB = v01 * wy0 + v11 * wy1;
                    const float s = rowA * wx0 + rowB * wx1;
                    A[c][j] = fmaf(T[j], s, A[c][j]);
                }
                T[j] = 0.0f;
            }
            break;   // group fully opaque: earlier layers + bg invisible
        } else {
            // Boundary path: full reference semantics (validity + clamps).
            const float wyv0 = (y0 >= 0 && y0 < HI) ? wy0 : 0.0f;
            const float wyv1 = (y1 >= 0 && y1 < HI) ? wy1 : 0.0f;
            const int y0c = min(max(y0, 0), HI - 1);
            const int y1c = min(max(y1, 0), HI - 1);
            const float my = wyv0 + wyv1;
            const float* r0 = sbase + y0c * WI;
            const float* r1 = sbase + y1c * WI;
#pragma unroll
            for (int j = 0; j < 4; j++) {
                const float ix = ix_at(px0 + j, p.x, p.y);
                const float x0f = floorf(ix);
                const float wx1 = ix - x0f;
                const float wx0 = 1.0f - wx1;
                const int   x0  = (int)x0f;
                const int   x1  = x0 + 1;
                const float wxv0 = (x0 >= 0 && x0 < WI) ? wx0 : 0.0f;
                const float wxv1 = (x1 >= 0 && x1 < WI) ? wx1 : 0.0f;
                const int x0c = min(max(x0, 0), WI - 1);
                const int x1c = min(max(x1, 0), WI - 1);

                const float m = my * (wxv0 + wxv1);
                if (m == 0.0f) continue;
                const float wgt = T[j] * m;
#pragma unroll
                for (int c = 0; c < CCH; c++) {
                    const float* rc0 = r0 + c * (HI * WI);
                    const float* rc1 = r1 + c * (HI * WI);
                    const float v00 = __ldg(rc0 + x0c);
                    const float v10 = __ldg(rc1 + x0c);
                    const float v01 = __ldg(rc0 + x1c);
                    const float v11 = __ldg(rc1 + x1c);
                    const float rowA = v00 * wyv0 + v10 * wyv1;
                    const float rowB = v01 * wyv0 + v11 * wyv1;
                    const float s = rowA * wxv0 + rowB * wxv1;
                    A[c][j] = fmaf(wgt, s, A[c][j]);
                }
                T[j] *= (1.0f - m);
            }
        }
    }

    // Background contribution only where transparency survives.
    const float Tm = fmaxf(fmaxf(T[0], T[1]), fmaxf(T[2], T[3]));
    if (Tm > 0.0f) {
        const float4 b0 = *reinterpret_cast<const float4*>(bg + base);
        const float4 b1 = *reinterpret_cast<const float4*>(bg + HW + base);
        const float4 b2 = *reinterpret_cast<const float4*>(bg + 2 * HW + base);
        A[0][0] = fmaf(b0.x, T[0], A[0][0]);
        A[0][1] = fmaf(b0.y, T[1], A[0][1]);
        A[0][2] = fmaf(b0.z, T[2], A[0][2]);
        A[0][3] = fmaf(b0.w, T[3], A[0][3]);
        A[1][0] = fmaf(b1.x, T[0], A[1][0]);
        A[1][1] = fmaf(b1.y, T[1], A[1][1]);
        A[1][2] = fmaf(b1.z, T[2], A[1][2]);
        A[1][3] = fmaf(b1.w, T[3], A[1][3]);
        A[2][0] = fmaf(b2.x, T[0], A[2][0]);
        A[2][1] = fmaf(b2.y, T[1], A[2][1]);
        A[2][2] = fmaf(b2.z, T[2], A[2][2]);
        A[2][3] = fmaf(b2.w, T[3], A[2][3]);
    }

    *reinterpret_cast<float4*>(out + base) =
        make_float4(A[0][0], A[0][1], A[0][2], A[0][3]);
    *reinterpret_cast<float4*>(out + HW + base) =
        make_float4(A[1][0], A[1][1], A[1][2], A[1][3]);
    *reinterpret_cast<float4*>(out + 2 * HW + base) =
        make_float4(A[2][0], A[2][1], A[2][2], A[2][3]);
}

extern "C" void kernel_launch(void* const* d_in, const int* in_sizes, int n_in,
                              void* d_out, int out_size) {
    const float* src  = (const float*)d_in[0];  // [8,3,512,512]
    const float* bg   = (const float*)d_in[1];  // [1,3,2048,2048]
    const float* coor = (const float*)d_in[2];  // [8,4]
    float* out = (float*)d_out;                 // [1,3,2048,2048]

    prm_kernel<<<1, 32>>>(coor);

    dim3 block(32, 4);                    // 128 threads
    dim3 grid(WO / (4 * 32), HO / 4);     // (16, 512) = 8192 blocks
    composite_kernel<<<grid, block>>>(src, bg, out);
}

// round 8
// speedup vs baseline: 1.4751x; 1.2554x over previous
#include <cuda_runtime.h>
#include <math.h>

// Problem constants
#define NIMG 8
#define CCH  3
#define HI   512
#define WI   512
#define HO   2048
#define WO   2048

__device__ __forceinline__ float sigm(float z) {
    return 1.0f / (1.0f + expf(-z));
}

// Single fused kernel: per-block param computation in shared memory, then
// back-to-front compositing with early termination (a fully-interior layer
// has m == 1 and overwrites everything below it).
// One thread = 4 consecutive x pixels; block (32,8) covers 128x8 px.
__global__ __launch_bounds__(256) void composite_kernel(
    const float* __restrict__ src,   // [8,3,512,512]
    const float* __restrict__ bg,    // [1,3,2048,2048]
    const float* __restrict__ coor,  // [8,4]
    float* __restrict__ out)         // [1,3,2048,2048]
{
    // Folded affine params: ix = ax*px + bx, iy = ay*py + by
    __shared__ float4 sprm[NIMG];

    const int ltid = threadIdx.y * 32 + threadIdx.x;
    if (ltid < NIMG) {
        const int n = ltid;
        float x = sigm(coor[4 * n + 0]) * (float)WO;
        float y = sigm(coor[4 * n + 1]) * (float)HO;
        float w = sigm(coor[4 * n + 2]) * (float)WO;
        float h = sigm(coor[4 * n + 3]) * (float)HO;
        float a  = (float)WO / (w + 1e-8f);
        float tx = (2.0f / (float)WO) * ((float)WO * 0.5f - x) * a;
        float b  = (float)HO / (h + 1e-8f);
        float ty = (2.0f / (float)HO) * ((float)HO * 0.5f - y) * b;
        // ix(px) = ((a*((2px+1)/WO - 1) + tx + 1)*WI - 1)/2  ==  ax*px + bx
        float ax = a * ((float)WI / (float)WO);
        float bx = ((a * (1.0f / (float)WO - 1.0f) + tx + 1.0f) * (float)WI - 1.0f) * 0.5f;
        float ay = b * ((float)HI / (float)HO);
        float by = ((b * (1.0f / (float)HO - 1.0f) + ty + 1.0f) * (float)HI - 1.0f) * 0.5f;
        sprm[n] = make_float4(ax, bx, ay, by);
    }
    __syncthreads();

    const int px0 = (blockIdx.x * 32 + threadIdx.x) * 4;
    const int py  = blockIdx.y * 8 + threadIdx.y;
    const int HW  = HO * WO;
    const int base = py * WO + px0;

    float A[3][4] = {{0.f,0.f,0.f,0.f},{0.f,0.f,0.f,0.f},{0.f,0.f,0.f,0.f}};
    float T[4] = {1.f, 1.f, 1.f, 1.f};

    const float fpy  = (float)py;
    const float fpx0 = (float)px0;

#pragma unroll
    for (int n = NIMG - 1; n >= 0; n--) {
        const float4 p = sprm[n];   // ax, bx, ay, by

        const float iy = fmaf(p.z, fpy, p.w);
        if (iy <= -1.0f || iy >= (float)HI) continue;

        // group x-range reject (ax > 0, ix monotone in px)
        const float ixA = fmaf(p.x, fpx0, p.y);
        const float ixB = fmaf(p.x, 3.0f, ixA);
        if (ixB <= -1.0f || ixA >= (float)WI) continue;

        const float y0f = floorf(iy);
        const float wy1 = iy - y0f;
        const float wy0 = 1.0f - wy1;
        const int   y0  = (int)y0f;
        const int   y1  = y0 + 1;
        const float* sbase = src + (size_t)n * CCH * HI * WI;

        const bool interior = (iy >= 0.0f) && (iy < (float)(HI - 1)) &&
                              (ixA >= 0.0f) && (ixB < (float)(WI - 1));

        if (interior) {
            // m == 1 for all 4 px: this layer overwrites everything below.
            const float* r0 = sbase + y0 * WI;
            const float* r1 = r0 + WI;
#pragma unroll
            for (int j = 0; j < 4; j++) {
                const float ix = fmaf(p.x, (float)j, ixA);
                const float x0f = floorf(ix);
                const float wx1 = ix - x0f;
                const float wx0 = 1.0f - wx1;
                const int   x0  = (int)x0f;
                const float w00 = wy0 * wx0, w10 = wy1 * wx0;
                const float w01 = wy0 * wx1, w11 = wy1 * wx1;
#pragma unroll
                for (int c = 0; c < CCH; c++) {
                    const float* rc0 = r0 + c * (HI * WI);
                    const float* rc1 = r1 + c * (HI * WI);
                    const float v00 = __ldg(rc0 + x0);
                    const float v10 = __ldg(rc1 + x0);
                    const float v01 = __ldg(rc0 + x0 + 1);
                    const float v11 = __ldg(rc1 + x0 + 1);
                    const float s = fmaf(v11, w11, fmaf(v10, w10,
                                    fmaf(v01, w01, v00 * w00)));
                    A[c][j] = fmaf(T[j], s, A[c][j]);
                }
                T[j] = 0.0f;
            }
            break;   // group fully opaque: earlier layers + bg invisible
        } else {
            // Boundary path: full reference semantics (validity + clamps).
            const float wyv0 = (y0 >= 0 && y0 < HI) ? wy0 : 0.0f;
            const float wyv1 = (y1 >= 0 && y1 < HI) ? wy1 : 0.0f;
            const int y0c = min(max(y0, 0), HI - 1);
            const int y1c = min(max(y1, 0), HI - 1);
            const float my = wyv0 + wyv1;
            const float* r0 = sbase + y0c * WI;
            const float* r1 = sbase + y1c * WI;
#pragma unroll
            for (int j = 0; j < 4; j++) {
                const float ix = fmaf(p.x, (float)j, ixA);
                const float x0f = floorf(ix);
                const float wx1 = ix - x0f;
                const float wx0 = 1.0f - wx1;
                const int   x0  = (int)x0f;
                const int   x1  = x0 + 1;
                const float wxv0 = (x0 >= 0 && x0 < WI) ? wx0 : 0.0f;
                const float wxv1 = (x1 >= 0 && x1 < WI) ? wx1 : 0.0f;
                const int x0c = min(max(x0, 0), WI - 1);
                const int x1c = min(max(x1, 0), WI - 1);

                const float m = my * (wxv0 + wxv1);
                if (m == 0.0f) continue;
                const float wgt = T[j] * m;
#pragma unroll
                for (int c = 0; c < CCH; c++) {
                    const float* rc0 = r0 + c * (HI * WI);
                    const float* rc1 = r1 + c * (HI * WI);
                    const float v00 = __ldg(rc0 + x0c);
                    const float v10 = __ldg(rc1 + x0c);
                    const float v01 = __ldg(rc0 + x1c);
                    const float v11 = __ldg(rc1 + x1c);
                    const float rowA = v00 * wyv0 + v10 * wyv1;
                    const float rowB = v01 * wyv0 + v11 * wyv1;
                    const float s = rowA * wxv0 + rowB * wxv1;
                    A[c][j] = fmaf(wgt, s, A[c][j]);
                }
                T[j] *= (1.0f - m);
            }
        }
    }

    // Background contribution only where transparency survives.
    const float Tm = fmaxf(fmaxf(T[0], T[1]), fmaxf(T[2], T[3]));
    if (Tm > 0.0f) {
        const float4 b0 = *reinterpret_cast<const float4*>(bg + base);
        const float4 b1 = *reinterpret_cast<const float4*>(bg + HW + base);
        const float4 b2 = *reinterpret_cast<const float4*>(bg + 2 * HW + base);
        A[0][0] = fmaf(b0.x, T[0], A[0][0]);
        A[0][1] = fmaf(b0.y, T[1], A[0][1]);
        A[0][2] = fmaf(b0.z, T[2], A[0][2]);
        A[0][3] = fmaf(b0.w, T[3], A[0][3]);
        A[1][0] = fmaf(b1.x, T[0], A[1][0]);
        A[1][1] = fmaf(b1.y, T[1], A[1][1]);
        A[1][2] = fmaf(b1.z, T[2], A[1][2]);
        A[1][3] = fmaf(b1.w, T[3], A[1][3]);
        A[2][0] = fmaf(b2.x, T[0], A[2][0]);
        A[2][1] = fmaf(b2.y, T[1], A[2][1]);
        A[2][2] = fmaf(b2.z, T[2], A[2][2]);
        A[2][3] = fmaf(b2.w, T[3], A[2][3]);
    }

    *reinterpret_cast<float4*>(out + base) =
        make_float4(A[0][0], A[0][1], A[0][2], A[0][3]);
    *reinterpret_cast<float4*>(out + HW + base) =
        make_float4(A[1][0], A[1][1], A[1][2], A[1][3]);
    *reinterpret_cast<float4*>(out + 2 * HW + base) =
        make_float4(A[2][0], A[2][1], A[2][2], A[2][3]);
}

extern "C" void kernel_launch(void* const* d_in, const int* in_sizes, int n_in,
                              void* d_out, int out_size) {
    const float* src  = (const float*)d_in[0];  // [8,3,512,512]
    const float* bg   = (const float*)d_in[1];  // [1,3,2048,2048]
    const float* coor = (const float*)d_in[2];  // [8,4]
    float* out = (float*)d_out;                 // [1,3,2048,2048]

    dim3 block(32, 8);
    dim3 grid(WO / (4 * 32), HO / 8);   // (16, 256)
    composite_kernel<<<grid, block>>>(src, bg, coor, out);
}